// round 11
// baseline (speedup 1.0000x reference)
#include <cuda_runtime.h>

#define NSTATE (1u << 22)

// swizzle on float4-unit index: bank-column = (u ^ (u>>3)) & 7
__device__ __forceinline__ int SW(int u) { return u ^ ((u >> 3) & 7); }

// half-CTA named barriers
#define BAR_HALF256(t) asm volatile("bar.sync %0, 256;" :: "r"(1 + ((t) >> 8)) : "memory")
#define BAR_HALF128(t) asm volatile("bar.sync %0, 128;" :: "r"(1 + ((t) >> 7)) : "memory")

// one 2x2 rotation butterfly: new = (c*I - i*s*X) * old
__device__ __forceinline__ void gate1(float& r0, float& i0, float& r1, float& i1,
                                      float c, float s)
{
    float nr0 = c * r0 + s * i1;
    float ni0 = c * i0 - s * r1;
    float nr1 = c * r1 + s * i0;
    float ni1 = c * i1 - s * r0;
    r0 = nr0; i0 = ni0; r1 = nr1; i1 = ni1;
}

// gate on a pair of interleaved units (each unit = 2 complex: r0,i0,r1,i1)
__device__ __forceinline__ void gateU(float4& A, float4& B, float c, float s)
{
    gate1(A.x, A.y, B.x, B.y, c, s);
    gate1(A.z, A.w, B.z, B.w, c, s);
}

// gate across two (R,I) float4 pairs, componentwise (4 complex each side)
__device__ __forceinline__ void gateV(float4& Ra, float4& Ia, float4& Rb, float4& Ib,
                                      float c, float s)
{
    gate1(Ra.x, Ia.x, Rb.x, Ib.x, c, s);
    gate1(Ra.y, Ia.y, Rb.y, Ib.y, c, s);
    gate1(Ra.z, Ia.z, Rb.z, Ib.z, c, s);
    gate1(Ra.w, Ia.w, Rb.w, Ib.w, c, s);
}

// per-CTA coefficient table: sc[a]=cos(angle[a]/2), ss[a]=sin(angle[a]/2).
// Complex bit b uses angle index 21-b.
#define MAKE_COEFS(ang, sc, ss, t)                                            \
    do {                                                                      \
        if ((t) < 22) {                                                       \
            float c_, s_;                                                     \
            sincosf(0.5f * __ldg((ang) + (t)), &s_, &c_);                     \
            (sc)[t] = c_; (ss)[t] = s_;                                       \
        }                                                                     \
    } while (0)

// 3 butterfly stages over U[8] with unit strides 1,2,4, angle idxs A0,A1,A2
#define STAGE3(A0, A1, A2)                                                    \
    do {                                                                      \
        float c0 = sc[A0], s0 = ss[A0], c1 = sc[A1], s1 = ss[A1];             \
        float c2 = sc[A2], s2 = ss[A2];                                       \
        _Pragma("unroll")                                                     \
        for (int p_ = 0; p_ < 8; ++p_)                                        \
            if (!(p_ & 1)) gateU(U[p_], U[p_ | 1], c0, s0);                   \
        _Pragma("unroll")                                                     \
        for (int p_ = 0; p_ < 8; ++p_)                                        \
            if (!(p_ & 2)) gateU(U[p_], U[p_ | 2], c1, s1);                   \
        _Pragma("unroll")                                                     \
        for (int p_ = 0; p_ < 8; ++p_)                                        \
            if (!(p_ & 4)) gateU(U[p_], U[p_ | 4], c2, s2);                   \
    } while (0)

// ---------------------------------------------------------------------------
// Kernel A: gates on complex bits 0..12 (angles 21..9).
// Tile = 8192 contiguous complex (64KB smem, 4096 units). 512 threads.
// Phases: fill(bits 0-3) |h| R2(4-6) |h| R3(7-9) |F| drain(10-12)+store.
// ---------------------------------------------------------------------------
__global__ void __launch_bounds__(512, 2) gateA(const float* __restrict__ xr,
                                                const float* __restrict__ xi,
                                                const float* __restrict__ ang,
                                                float* __restrict__ outr,
                                                float* __restrict__ outi)
{
    extern __shared__ float4 sm[];            // 4096 units = 64KB
    __shared__ float sc[22], ss[22];
    const int t = threadIdx.x;
    const unsigned base = (unsigned)blockIdx.x << 13;

    MAKE_COEFS(ang, sc, ss, t);

    // ---- fill: 16 contiguous complex/thread, gate bits 0..3 ----
    {
        float4 R[4], I[4];
        const float4* pr = reinterpret_cast<const float4*>(xr + base) + t * 4;
        const float4* pi = reinterpret_cast<const float4*>(xi + base) + t * 4;
#pragma unroll
        for (int q = 0; q < 4; ++q) { R[q] = pr[q]; I[q] = pi[q]; }

        __syncthreads();                      // coefs ready (after LDG issue)

        float c0 = sc[21], s0 = ss[21], c1 = sc[20], s1 = ss[20];
        float c2 = sc[19], s2 = ss[19], c3 = sc[18], s3 = ss[18];
#pragma unroll
        for (int q = 0; q < 4; ++q) {         // bit 0
            gate1(R[q].x, I[q].x, R[q].y, I[q].y, c0, s0);
            gate1(R[q].z, I[q].z, R[q].w, I[q].w, c0, s0);
        }
#pragma unroll
        for (int q = 0; q < 4; ++q) {         // bit 1
            gate1(R[q].x, I[q].x, R[q].z, I[q].z, c1, s1);
            gate1(R[q].y, I[q].y, R[q].w, I[q].w, c1, s1);
        }
        gateV(R[0], I[0], R[1], I[1], c2, s2);   // bit 2
        gateV(R[2], I[2], R[3], I[3], c2, s2);
        gateV(R[0], I[0], R[2], I[2], c3, s3);   // bit 3
        gateV(R[1], I[1], R[3], I[3], c3, s3);

#pragma unroll
        for (int m = 0; m < 8; ++m) {
            int q = m >> 1;
            float4 u = (m & 1) ? make_float4(R[q].z, I[q].z, R[q].w, I[q].w)
                               : make_float4(R[q].x, I[q].x, R[q].y, I[q].y);
            sm[SW(t * 8 + m)] = u;
        }
    }
    BAR_HALF256(t);

    float4 U[8];

    // ---- R2: gates bits 4-6 (unit bits 3-5), angles 17,16,15 ----
    {
        const int lo = t & 7, hi = t >> 3;
#pragma unroll
        for (int j = 0; j < 8; ++j) U[j] = sm[SW((hi << 6) | (j << 3) | lo)];
        STAGE3(17, 16, 15);
#pragma unroll
        for (int j = 0; j < 8; ++j) sm[SW((hi << 6) | (j << 3) | lo)] = U[j];
    }
    BAR_HALF256(t);

    // ---- R3: gates bits 7-9 (unit bits 6-8), angles 14,13,12 ----
    {
        const int lo = t & 63, hi = t >> 6;
#pragma unroll
        for (int j = 0; j < 8; ++j) U[j] = sm[SW((hi << 9) | (j << 6) | lo)];
        STAGE3(14, 13, 12);
#pragma unroll
        for (int j = 0; j < 8; ++j) sm[SW((hi << 9) | (j << 6) | lo)] = U[j];
    }
    __syncthreads();                          // drain crosses CTA halves

    // ---- drain: gates bits 10-12 (unit bits 9-11), angles 11,10,9; store ----
    {
#pragma unroll
        for (int j = 0; j < 8; ++j) U[j] = sm[SW((j << 9) | t)];
        STAGE3(11, 10, 9);
#pragma unroll
        for (int j = 0; j < 8; ++j) {
            unsigned c = base + ((unsigned)j << 10) + 2u * (unsigned)t;
            float4 A = U[j];
            *reinterpret_cast<float2*>(outr + c) = make_float2(A.x, A.z);
            *reinterpret_cast<float2*>(outi + c) = make_float2(A.y, A.w);
        }
    }
}

// ---------------------------------------------------------------------------
// Kernel B: gates on complex bits 13..21 (angles 8..0). In-place on out.
// Tile = 8 contiguous (bits 0-2, passive) x 512 strided h (bits 13-21).
// 256 threads, 32KB STATIC smem -> 4 CTAs/SM. Unit u = (h<<2)|w holds
// complex (h, lo = 2w, 2w+1) as (r,i,r,i); thread owns one lo-pair (w = t&3)
// across 8 h-values per phase. Global rows 32B (one sector), lanes 0-3/row.
// Phases: fill+gates(h6-h8) |F| r1(h0-h2) |h128| drain(h3-h5)+store.
// ---------------------------------------------------------------------------
__global__ void __launch_bounds__(256, 4) gateB(float* __restrict__ dr,
                                                float* __restrict__ di,
                                                const float* __restrict__ ang)
{
    __shared__ float4 sm[2048];               // 32KB
    __shared__ float sc[22], ss[22];
    const int t = threadIdx.x;
    const unsigned base = (unsigned)blockIdx.x << 3;   // complex bits 3-12

    MAKE_COEFS(ang, sc, ss, t);

    float4 U[8];
    const int w = t & 3;                      // lo-pair slot (lo = 2w, 2w+1)

    // ---- fill + gates h6,h7,h8 (bits 19-21, angles 2,1,0) ----
    {
        const int hm = t >> 2;                // h bits 0..5
#pragma unroll
        for (int j = 0; j < 8; ++j) {         // j = h bits 6-8
            unsigned h = ((unsigned)j << 6) | (unsigned)hm;
            unsigned g = (h << 13) + base + 2u * (unsigned)w;
            float2 R = *reinterpret_cast<const float2*>(dr + g);
            float2 I = *reinterpret_cast<const float2*>(di + g);
            U[j] = make_float4(R.x, I.x, R.y, I.y);
        }
        __syncthreads();                      // coefs ready (after LDG issue)
        STAGE3(2, 1, 0);
#pragma unroll
        for (int j = 0; j < 8; ++j)
            sm[SW((j << 8) | (hm << 2) | w)] = U[j];
    }
    __syncthreads();                          // fill->r1 crosses CTA halves

    // ---- r1: gates h0,h1,h2 (bits 13-15, angles 8,7,6) ----
    {
        const int hh = t >> 2;                // h bits 3..8
#pragma unroll
        for (int j = 0; j < 8; ++j) U[j] = sm[SW((hh << 5) | (j << 2) | w)];
        STAGE3(8, 7, 6);
#pragma unroll
        for (int j = 0; j < 8; ++j) sm[SW((hh << 5) | (j << 2) | w)] = U[j];
    }
    BAR_HALF128(t);                           // r1->drain half-local (u bit 10)

    // ---- drain: gates h3,h4,h5 (bits 16-18, angles 5,4,3); store ----
    {
        const int hb = (t >> 2) & 7;          // h bits 0..2
        const int ht = t >> 5;                // h bits 6..8
#pragma unroll
        for (int j = 0; j < 8; ++j)           // j = h bits 3-5
            U[j] = sm[SW((ht << 8) | (j << 5) | (hb << 2) | w)];
        STAGE3(5, 4, 3);
#pragma unroll
        for (int j = 0; j < 8; ++j) {
            unsigned h = ((unsigned)ht << 6) | ((unsigned)j << 3) | (unsigned)hb;
            unsigned g = (h << 13) + base + 2u * (unsigned)w;
            float4 A = U[j];
            *reinterpret_cast<float2*>(dr + g) = make_float2(A.x, A.z);
            *reinterpret_cast<float2*>(di + g) = make_float2(A.y, A.w);
        }
    }
}

extern "C" void kernel_launch(void* const* d_in, const int* in_sizes, int n_in,
                              void* d_out, int out_size)
{
    const float* xr  = (const float*)d_in[0];
    const float* xi  = (const float*)d_in[1];
    const float* ang = (const float*)d_in[2];
    float* outr = (float*)d_out;
    float* outi = outr + NSTATE;

    const int shA = 4096 * sizeof(float4);    // 64KB
    cudaFuncSetAttribute(gateA, cudaFuncAttributeMaxDynamicSharedMemorySize, shA);

    // Pass 1: gates on bits 0..12 (input -> out)
    gateA<<<NSTATE / 8192, 512, shA>>>(xr, xi, ang, outr, outi);

    // Pass 2: gates on bits 13..21 (in-place on out), 4 CTAs/SM
    gateB<<<NSTATE / 4096, 256>>>(outr, outi, ang);
}